// round 5
// baseline (speedup 1.0000x reference)
#include <cuda_runtime.h>
#include <math.h>

#define B_DIM 64
#define S_DIM 1000
#define K_DIM 12
#define N_DIM 80
#define NP 81
#define EPS 1e-5f
#define LOG_2PI 1.8378770664093453f

// Scratch (device globals: no allocation allowed anywhere)
__device__ float g_W[B_DIM * K_DIM * N_DIM * N_DIM];   // W[i][j] = (L^{-T})[i][j], i-major, upper-tri (0 below)
__device__ float g_c[B_DIM * K_DIM * N_DIM];           // c = L^{-1} mu
__device__ float g_cst[B_DIM * K_DIM];                 // -logdet_half - 0.5*N*log(2pi)

typedef unsigned long long ull;

#define PACK2(d, lo, hi)   asm("mov.b64 %0, {%1, %2};" : "=l"(d) : "f"(lo), "f"(hi))
#define UNPACK2(lo, hi, s) asm("mov.b64 {%0, %1}, %2;" : "=f"(lo), "=f"(hi) : "l"(s))
#define FMA2(d, a, b, c)   asm("fma.rn.f32x2 %0, %1, %2, %3;" : "=l"(d) : "l"(a), "l"(b), "l"(c))
#define ADD2(d, a, b)      asm("add.rn.f32x2 %0, %1, %2;" : "=l"(d) : "l"(a), "l"(b))

// ---------------------------------------------------------------------------
// Prep per (b,k), 128 threads:
//  1) LDL^T in place (lower), trailing update parallel over ALL triangle elems.
//  2) Normalize to Cholesky L; rs[j] = 1/L[j][j]; logdet.
//  3) Half-blocked inversion M = L^{-1}: two 40x40 column-parallel triangular
//     inversions + M10 = -M11 * (L10 * M00) as thread-parallel GEMMs.
//     Storage: M[i][j] (i>j) at A[j*NP+i] (upper); diag M = rs.
//  4) c = M*mu, W = M^T, cst.
// ---------------------------------------------------------------------------
__global__ void __launch_bounds__(128) prep_kernel(const float* __restrict__ mu,
                                                   const float* __restrict__ sigma) {
    __shared__ float A[N_DIM * NP];     // 25.9 KB
    __shared__ float Tb[40 * 41];       // 6.6 KB  (L10 * M00)
    __shared__ float rs[N_DIM];         // rsqrt(D) = 1/L[j][j]
    __shared__ float lg[N_DIM];         // 0.5*log(D)
    __shared__ float invj_s;

    int bk = blockIdx.x;
    int tid = threadIdx.x;

    const float* sig = sigma + (size_t)bk * N_DIM * N_DIM;
    for (int p = tid; p < N_DIM * N_DIM; p += 128) {
        int i = p / N_DIM, j = p % N_DIM;
        float v = sig[p];
        if (i == j) v += EPS;
        A[i * NP + j] = v;
    }
    __syncthreads();

    // ---- LDL^T (unnormalized in-place: A[i][j] = Lu[i][j]*D_j for i>j, diag = D_j)
    for (int j = 0; j < N_DIM - 1; j++) {
        if (tid == 0) invj_s = 1.0f / A[j * NP + j];
        __syncthreads();
        float invj = invj_s;
        int m = N_DIM - 1 - j;           // trailing size
        int T = m * (m + 1) / 2;         // elements incl diagonal
        int chunk = (T + 127) >> 7;
        int start = tid * chunk;
        int end = start + chunk;
        if (end > T) end = T;
        if (start < T) {
            // linear triangle index -> (row offset rr, col offset cc), row-major
            int rr = (int)((sqrtf(8.0f * (float)start + 1.0f) - 1.0f) * 0.5f);
            while ((rr * (rr + 1)) / 2 > start) rr--;
            while (((rr + 1) * (rr + 2)) / 2 <= start) rr++;
            int cc = start - (rr * (rr + 1)) / 2;
            int r = j + 1 + rr, c = j + 1 + cc;
            for (int p = start; p < end; p++) {
                A[r * NP + c] -= A[r * NP + j] * (invj * A[c * NP + j]);
                if (++c > r) { r++; c = j + 1; }
            }
        }
        __syncthreads();
    }

    // ---- diag: rs, log
    if (tid < N_DIM) {
        float d = A[tid * NP + tid];
        rs[tid] = rsqrtf(d);
        lg[tid] = 0.5f * logf(d);
    }
    __syncthreads();

    // ---- normalize to Cholesky L: for i>=j: A[i][j] *= rs[j]  (diag -> sqrt(D))
    for (int p = tid; p < N_DIM * N_DIM; p += 128) {
        int i = p / N_DIM, j = p % N_DIM;
        if (i >= j) A[i * NP + j] *= rs[j];
    }
    if (tid == 0) {
        float s = 0.f;
        for (int j = 0; j < N_DIM; j++) s += lg[j];
        g_cst[bk] = -s - 0.5f * N_DIM * LOG_2PI;
    }
    __syncthreads();

    // ---- two independent 40x40 triangular inversions (one column per thread)
    if (tid < N_DIM) {
        int j = tid;
        int hi = (j < 40) ? 40 : 80;
        for (int i = j + 1; i < hi; i++) {
            float s = A[i * NP + j] * rs[j];               // L[i][j]*M[j][j]
            for (int t = j + 1; t < i; t++)
                s += A[i * NP + t] * A[j * NP + t];        // L[i][t]*M[t][j]
            A[j * NP + i] = -s * rs[i];
        }
    }
    __syncthreads();

    // ---- Tb = L10 * M00   (Tb[t][j], t,j in 0..39; global L row 40+t)
    for (int p = tid; p < 1600; p += 128) {
        int ii = p / 40, jj = p % 40;
        float s = A[(40 + ii) * NP + jj] * rs[jj];
        for (int t = jj + 1; t < 40; t++)
            s += A[(40 + ii) * NP + t] * A[jj * NP + t];
        Tb[ii * 41 + jj] = s;
    }
    __syncthreads();

    // ---- M10 = -M11 * Tb ; store at A[jj*NP + 40+ii]
    for (int p = tid; p < 1600; p += 128) {
        int ii = p / 40, jj = p % 40;
        float s = rs[40 + ii] * Tb[ii * 41 + jj];
        for (int t = 0; t < ii; t++)
            s += A[(40 + t) * NP + (40 + ii)] * Tb[t * 41 + jj];
        A[jj * NP + (40 + ii)] = -s;
    }
    __syncthreads();

    // ---- c = M * mu ; W = M^T
    const float* mub = mu + (size_t)bk * N_DIM;
    if (tid < N_DIM) {
        int j = tid;
        float c = mub[j] * rs[j];
        for (int i = 0; i < j; i++) c += mub[i] * A[i * NP + j];
        g_c[bk * N_DIM + j] = c;
    }
    float* wout = g_W + (size_t)bk * N_DIM * N_DIM;
    for (int p = tid; p < N_DIM * N_DIM; p += 128) {
        int i = p / N_DIM, j = p % N_DIM;
        float w = 0.f;
        if (i < j)       w = A[i * NP + j];
        else if (i == j) w = rs[i];
        wout[p] = w;
    }
}

// ---------------------------------------------------------------------------
// Main: out[b][s][k] = -0.5*||x_s @ W_k - c_k||^2 + cst_k
// Block = (b, s-tile of 125 rows), 128 threads, 1 row/thread.
// x staged as i-pair float2 in smem (LDS.64 per 2 i's, conflict-free);
// W_k staged in smem, broadcast LDS.128 -> f32x2 FMA pairs over 16-wide j groups.
// ---------------------------------------------------------------------------
__global__ void __launch_bounds__(128, 3) ll_kernel(const float* __restrict__ x,
                                                    float* __restrict__ out) {
    extern __shared__ float sm[];
    float2* xs2   = (float2*)sm;                    // 40 i-pairs * 125 rows (40 KB)
    float*  Ws    = sm + 40 * 125 * 2;              // 6400 floats (25.6 KB)
    float*  csh   = Ws + N_DIM * N_DIM;             // 80 (holds -c)
    float*  cst_sh = csh + N_DIM;                   // 1

    int b    = blockIdx.x;
    int tile = blockIdx.y;
    int tid  = threadIdx.x;
    int s0   = tile * 125;

    // Stage x: coalesced global reads; scalar scatter into (i-pair, row) float2 layout
    const float* xb = x + ((size_t)b * S_DIM + s0) * N_DIM;
    float* xsf = (float*)xs2;
    for (int p = tid; p < 125 * N_DIM; p += 128) {
        int r = p / N_DIM, i = p % N_DIM;
        xsf[(i >> 1) * 250 + (r << 1) + (i & 1)] = xb[p];
    }

    bool active = (tid < 125);

    for (int k = 0; k < K_DIM; k++) {
        __syncthreads();
        int bk = b * K_DIM + k;
        const float4* wg = (const float4*)(g_W + (size_t)bk * (N_DIM * N_DIM));
        float4* wd = (float4*)Ws;
        for (int p = tid; p < (N_DIM * N_DIM) / 4; p += 128) wd[p] = wg[p];
        for (int p = tid; p < N_DIM; p += 128) csh[p] = -g_c[bk * N_DIM + p];
        if (tid == 0) *cst_sh = g_cst[bk];
        __syncthreads();

        if (active) {
            ull acc = 0ULL;
            #pragma unroll 1
            for (int g = 0; g < 5; g++) {
                const int j0 = g * 16;
                ull y[8];
                #pragma unroll
                for (int q = 0; q < 8; q++) y[q] = 0ULL;
                const int ipb = (g + 1) * 8;   // i-pairs (triangular: i < 16(g+1))
                #pragma unroll 4
                for (int ip = 0; ip < ipb; ip++) {
                    float2 xp = xs2[ip * 125 + tid];
                    ull xa, xc;
                    PACK2(xa, xp.x, xp.x);
                    PACK2(xc, xp.y, xp.y);
                    const ulonglong2* w0 = (const ulonglong2*)(Ws + (2 * ip) * N_DIM + j0);
                    const ulonglong2* w1 = (const ulonglong2*)(Ws + (2 * ip + 1) * N_DIM + j0);
                    #pragma unroll
                    for (int q = 0; q < 4; q++) {
                        ulonglong2 wa = w0[q];                 // broadcast LDS.128
                        FMA2(y[2 * q],     xa, wa.x, y[2 * q]);
                        FMA2(y[2 * q + 1], xa, wa.y, y[2 * q + 1]);
                    }
                    #pragma unroll
                    for (int q = 0; q < 4; q++) {
                        ulonglong2 wb = w1[q];
                        FMA2(y[2 * q],     xc, wb.x, y[2 * q]);
                        FMA2(y[2 * q + 1], xc, wb.y, y[2 * q + 1]);
                    }
                }
                const ull* ncp = (const ull*)(csh + j0);
                #pragma unroll
                for (int q = 0; q < 8; q++) {
                    ull nc = ncp[q];
                    ull d0;
                    ADD2(d0, y[q], nc);
                    FMA2(acc, d0, d0, acc);
                }
            }
            float a0, a1;
            UNPACK2(a0, a1, acc);
            out[((size_t)b * S_DIM + s0 + tid) * K_DIM + k] =
                fmaf(-0.5f, a0 + a1, *cst_sh);
        }
    }
}

// ---------------------------------------------------------------------------
extern "C" void kernel_launch(void* const* d_in, const int* in_sizes, int n_in,
                              void* d_out, int out_size) {
    const float* x     = (const float*)d_in[0];
    const float* mu    = (const float*)d_in[1];
    const float* sigma = (const float*)d_in[2];
    float* out = (float*)d_out;

    prep_kernel<<<B_DIM * K_DIM, 128>>>(mu, sigma);

    int smem = (40 * 125 * 2 + N_DIM * N_DIM + N_DIM + 4) * (int)sizeof(float);
    cudaFuncSetAttribute(ll_kernel, cudaFuncAttributeMaxDynamicSharedMemorySize, smem);
    ll_kernel<<<dim3(B_DIM, 8), 128, smem>>>(x, out);
}

// round 6
// speedup vs baseline: 1.1805x; 1.1805x over previous
#include <cuda_runtime.h>
#include <math.h>

#define B_DIM 64
#define S_DIM 1000
#define K_DIM 12
#define N_DIM 80
#define NP 81
#define EPS 1e-5f
#define LOG_2PI 1.8378770664093453f

// Scratch (device globals: no allocation allowed anywhere)
__device__ float g_W[B_DIM * K_DIM * N_DIM * N_DIM];   // W[i][j] = (L^{-T})[i][j], i-major, upper-tri
__device__ float g_c[B_DIM * K_DIM * N_DIM];           // c = L^{-1} mu
__device__ float g_cst[B_DIM * K_DIM];                 // -logdet_half - 0.5*N*log(2pi)
__device__ float g_xT[B_DIM * N_DIM * S_DIM];          // x transposed: [b][i][s]

typedef unsigned long long ull;

#define PACK2(d, lo, hi)   asm("mov.b64 %0, {%1, %2};" : "=l"(d) : "f"(lo), "f"(hi))
#define UNPACK2(lo, hi, s) asm("mov.b64 {%0, %1}, %2;" : "=f"(lo), "=f"(hi) : "l"(s))
#define FMA2(d, a, b, c)   asm("fma.rn.f32x2 %0, %1, %2, %3;" : "=l"(d) : "l"(a), "l"(b), "l"(c))
#define ADD2(d, a, b)      asm("add.rn.f32x2 %0, %1, %2;" : "=l"(d) : "l"(a), "l"(b))

// ---------------------------------------------------------------------------
// Transpose x[b][s][i] -> g_xT[b][i][s]. Standard 32x32 smem tile.
// ---------------------------------------------------------------------------
__global__ void __launch_bounds__(256) transpose_kernel(const float* __restrict__ x) {
    __shared__ float t[32][33];
    int b = blockIdx.z;
    int s_base = blockIdx.x * 32;
    int i_base = blockIdx.y * 32;
    int tx = threadIdx.x, ty = threadIdx.y;   // (32, 8)
    const float* xb = x + (size_t)b * S_DIM * N_DIM;
    #pragma unroll
    for (int q = 0; q < 4; q++) {
        int s = s_base + ty + q * 8;
        int i = i_base + tx;
        if (s < S_DIM && i < N_DIM) t[ty + q * 8][tx] = xb[s * N_DIM + i];
    }
    __syncthreads();
    float* xTb = g_xT + (size_t)b * N_DIM * S_DIM;
    #pragma unroll
    for (int q = 0; q < 4; q++) {
        int i = i_base + ty + q * 8;
        int s = s_base + tx;
        if (s < S_DIM && i < N_DIM) xTb[i * S_DIM + s] = t[tx][ty + q * 8];
    }
}

// ---------------------------------------------------------------------------
// Prep per (b,k), 128 threads:
//  1) LDL^T in place (lower): per pivot column j, one COLUMN of the trailing
//     submatrix per thread (branch-free inner loop, broadcast pivot reads).
//  2) Normalize to Cholesky L; rs[j] = 1/L[j][j]; logdet.
//  3) Half-blocked inversion M = L^{-1}: two 40x40 column-parallel triangular
//     inversions + M10 = -M11 * (L10 * M00).
//     Storage: M[i][j] (i>j) at A[j*NP+i] (upper); diag M = rs.
//  4) c = M*mu, W = M^T, cst.
// ---------------------------------------------------------------------------
__global__ void __launch_bounds__(128) prep_kernel(const float* __restrict__ mu,
                                                   const float* __restrict__ sigma) {
    __shared__ float A[N_DIM * NP];
    __shared__ float Tb[40 * 41];
    __shared__ float rs[N_DIM];
    __shared__ float lg[N_DIM];
    __shared__ float invj_s;

    int bk = blockIdx.x;
    int tid = threadIdx.x;

    const float* sig = sigma + (size_t)bk * N_DIM * N_DIM;
    for (int p = tid; p < N_DIM * N_DIM; p += 128) {
        int i = p / N_DIM, j = p % N_DIM;
        float v = sig[p];
        if (i == j) v += EPS;
        A[i * NP + j] = v;
    }
    __syncthreads();

    // ---- LDL^T: pivot j, thread t updates trailing column c = j+1+t
    for (int j = 0; j < N_DIM - 1; j++) {
        if (tid == 0) invj_s = 1.0f / A[j * NP + j];
        __syncthreads();
        float invj = invj_s;
        int c = j + 1 + tid;
        if (c < N_DIM) {
            float f = invj * A[c * NP + j];
            #pragma unroll 4
            for (int r = c; r < N_DIM; r++)
                A[r * NP + c] -= A[r * NP + j] * f;   // col-j reads broadcast/strided, conflict-free (NP odd)
        }
        __syncthreads();
    }

    // ---- diag: rs, log
    if (tid < N_DIM) {
        float d = A[tid * NP + tid];
        rs[tid] = rsqrtf(d);
        lg[tid] = 0.5f * logf(d);
    }
    __syncthreads();

    // ---- normalize to Cholesky L
    for (int p = tid; p < N_DIM * N_DIM; p += 128) {
        int i = p / N_DIM, j = p % N_DIM;
        if (i >= j) A[i * NP + j] *= rs[j];
    }
    if (tid == 0) {
        float s = 0.f;
        for (int j = 0; j < N_DIM; j++) s += lg[j];
        g_cst[bk] = -s - 0.5f * N_DIM * LOG_2PI;
    }
    __syncthreads();

    // ---- two independent 40x40 triangular inversions (one column per thread)
    if (tid < N_DIM) {
        int j = tid;
        int hi = (j < 40) ? 40 : 80;
        for (int i = j + 1; i < hi; i++) {
            float s = A[i * NP + j] * rs[j];
            for (int t = j + 1; t < i; t++)
                s += A[i * NP + t] * A[j * NP + t];
            A[j * NP + i] = -s * rs[i];
        }
    }
    __syncthreads();

    // ---- Tb = L10 * M00
    for (int p = tid; p < 1600; p += 128) {
        int ii = p / 40, jj = p % 40;
        float s = A[(40 + ii) * NP + jj] * rs[jj];
        for (int t = jj + 1; t < 40; t++)
            s += A[(40 + ii) * NP + t] * A[jj * NP + t];
        Tb[ii * 41 + jj] = s;
    }
    __syncthreads();

    // ---- M10 = -M11 * Tb
    for (int p = tid; p < 1600; p += 128) {
        int ii = p / 40, jj = p % 40;
        float s = rs[40 + ii] * Tb[ii * 41 + jj];
        for (int t = 0; t < ii; t++)
            s += A[(40 + t) * NP + (40 + ii)] * Tb[t * 41 + jj];
        A[jj * NP + (40 + ii)] = -s;
    }
    __syncthreads();

    // ---- c = M * mu ; W = M^T
    const float* mub = mu + (size_t)bk * N_DIM;
    if (tid < N_DIM) {
        int j = tid;
        float c = mub[j] * rs[j];
        for (int i = 0; i < j; i++) c += mub[i] * A[i * NP + j];
        g_c[bk * N_DIM + j] = c;
    }
    float* wout = g_W + (size_t)bk * N_DIM * N_DIM;
    for (int p = tid; p < N_DIM * N_DIM; p += 128) {
        int i = p / N_DIM, j = p % N_DIM;
        float w = 0.f;
        if (i < j)       w = A[i * NP + j];
        else if (i == j) w = rs[i];
        wout[p] = w;
    }
}

// ---------------------------------------------------------------------------
// Main: out[b][s][k] = -0.5*||x_s @ W_k - c_k||^2 + cst_k
// Grid (64, 2 tiles of 500 rows, 4 k-splits of 3). Block 128 (125 active).
// Thread owns rows {t, t+125, t+250, t+375}; x read coalesced from g_xT
// (L1/L2 cached, no smem); W broadcast via LDS.128; f32x2 FMA pairs.
// Triangular: j-groups of 16, i < 16(g+1).
// ---------------------------------------------------------------------------
__global__ void __launch_bounds__(128, 3) ll_kernel(float* __restrict__ out) {
    __shared__ float Ws[N_DIM * N_DIM];   // 25.6 KB
    __shared__ float csh[N_DIM];          // -c
    __shared__ float cst_sh;

    int b    = blockIdx.x;
    int tile = blockIdx.y;
    int kz   = blockIdx.z;
    int tid  = threadIdx.x;
    int s0   = tile * 500;

    const float* xTb = g_xT + (size_t)b * N_DIM * S_DIM + s0 + tid;
    bool active = (tid < 125);

    for (int kk = 0; kk < 3; kk++) {
        int k = kz * 3 + kk;
        int bk = b * K_DIM + k;
        __syncthreads();
        const float4* wg = (const float4*)(g_W + (size_t)bk * (N_DIM * N_DIM));
        float4* wd = (float4*)Ws;
        for (int p = tid; p < (N_DIM * N_DIM) / 4; p += 128) wd[p] = wg[p];
        for (int p = tid; p < N_DIM; p += 128) csh[p] = -g_c[bk * N_DIM + p];
        if (tid == 0) cst_sh = g_cst[bk];
        __syncthreads();

        if (active) {
            ull accq0 = 0ULL, accq1 = 0ULL, accq2 = 0ULL, accq3 = 0ULL;
            #pragma unroll 1
            for (int g = 0; g < 5; g++) {
                const int j0 = g * 16;
                ull y0[8], y1[8], y2[8], y3[8];
                #pragma unroll
                for (int q = 0; q < 8; q++) { y0[q] = 0ULL; y1[q] = 0ULL; y2[q] = 0ULL; y3[q] = 0ULL; }
                const int ibound = 16 * (g + 1);
                #pragma unroll 4
                for (int i = 0; i < ibound; i++) {
                    const float* xcol = xTb + i * S_DIM;
                    float xv0 = xcol[0];
                    float xv1 = xcol[125];
                    float xv2 = xcol[250];
                    float xv3 = xcol[375];
                    ull p0, p1, p2, p3;
                    PACK2(p0, xv0, xv0);
                    PACK2(p1, xv1, xv1);
                    PACK2(p2, xv2, xv2);
                    PACK2(p3, xv3, xv3);
                    const ulonglong2* wp = (const ulonglong2*)(Ws + i * N_DIM + j0);
                    #pragma unroll
                    for (int q = 0; q < 4; q++) {
                        ulonglong2 w = wp[q];      // broadcast LDS.128: 4 W floats = 2 j-pairs
                        FMA2(y0[2 * q],     p0, w.x, y0[2 * q]);
                        FMA2(y0[2 * q + 1], p0, w.y, y0[2 * q + 1]);
                        FMA2(y1[2 * q],     p1, w.x, y1[2 * q]);
                        FMA2(y1[2 * q + 1], p1, w.y, y1[2 * q + 1]);
                        FMA2(y2[2 * q],     p2, w.x, y2[2 * q]);
                        FMA2(y2[2 * q + 1], p2, w.y, y2[2 * q + 1]);
                        FMA2(y3[2 * q],     p3, w.x, y3[2 * q]);
                        FMA2(y3[2 * q + 1], p3, w.y, y3[2 * q + 1]);
                    }
                }
                // epilogue: (y - c)^2 accumulated as pairs (csh holds -c)
                const ull* ncp = (const ull*)(csh + j0);
                #pragma unroll
                for (int q = 0; q < 8; q++) {
                    ull nc = ncp[q];
                    ull d0, d1, d2, d3;
                    ADD2(d0, y0[q], nc); FMA2(accq0, d0, d0, accq0);
                    ADD2(d1, y1[q], nc); FMA2(accq1, d1, d1, accq1);
                    ADD2(d2, y2[q], nc); FMA2(accq2, d2, d2, accq2);
                    ADD2(d3, y3[q], nc); FMA2(accq3, d3, d3, accq3);
                }
            }
            float cst = cst_sh;
            float a0, a1;
            size_t base = ((size_t)b * S_DIM + s0 + tid) * K_DIM + k;
            UNPACK2(a0, a1, accq0);
            out[base]                        = fmaf(-0.5f, a0 + a1, cst);
            UNPACK2(a0, a1, accq1);
            out[base + (size_t)125 * K_DIM]  = fmaf(-0.5f, a0 + a1, cst);
            UNPACK2(a0, a1, accq2);
            out[base + (size_t)250 * K_DIM]  = fmaf(-0.5f, a0 + a1, cst);
            UNPACK2(a0, a1, accq3);
            out[base + (size_t)375 * K_DIM]  = fmaf(-0.5f, a0 + a1, cst);
        }
    }
}

// ---------------------------------------------------------------------------
extern "C" void kernel_launch(void* const* d_in, const int* in_sizes, int n_in,
                              void* d_out, int out_size) {
    const float* x     = (const float*)d_in[0];
    const float* mu    = (const float*)d_in[1];
    const float* sigma = (const float*)d_in[2];
    float* out = (float*)d_out;

    transpose_kernel<<<dim3(32, 3, B_DIM), dim3(32, 8)>>>(x);
    prep_kernel<<<B_DIM * K_DIM, 128>>>(mu, sigma);
    ll_kernel<<<dim3(B_DIM, 2, 4), 128>>>(out);
}

// round 8
// speedup vs baseline: 1.2610x; 1.0682x over previous
#include <cuda_runtime.h>
#include <cuda_bf16.h>
#include <math.h>
#include <stdint.h>

#define B_DIM 64
#define S_DIM 1000
#define K_DIM 12
#define N_DIM 80
#define NP 81
#define EPS 1e-5f
#define LOG_2PI 1.8378770664093453f

// ---- device scratch (no allocations allowed) ----
__device__ float         g_cst[B_DIM * K_DIM];
__device__ float         g_c[B_DIM * K_DIM * N_DIM];
__device__ __nv_bfloat16 g_xhi[B_DIM * S_DIM * N_DIM];
__device__ __nv_bfloat16 g_xlo[B_DIM * S_DIM * N_DIM];
// B operand pre-packed as m16n8k16 B-fragment image:
// idx = bk*1600 + ((kc*4+t)*80 + n);  .x = pack(W[kc*16+2t][n], W[kc*16+2t+1][n])
//                                     .y = pack(W[kc*16+2t+8][n], W[kc*16+2t+9][n])
__device__ uint2         g_wqhi[B_DIM * K_DIM * 1600];
__device__ uint2         g_wqlo[B_DIM * K_DIM * 1600];

__device__ __forceinline__ uint32_t pack_bf16(__nv_bfloat16 lo, __nv_bfloat16 hi) {
    return (uint32_t)__bfloat16_as_ushort(lo) | ((uint32_t)__bfloat16_as_ushort(hi) << 16);
}

__device__ __forceinline__ void mma16816(float d[4], const uint32_t a[4], uint32_t b0, uint32_t b1) {
    asm volatile(
        "mma.sync.aligned.m16n8k16.row.col.f32.bf16.bf16.f32 "
        "{%0,%1,%2,%3}, {%4,%5,%6,%7}, {%8,%9}, {%0,%1,%2,%3};"
        : "+f"(d[0]), "+f"(d[1]), "+f"(d[2]), "+f"(d[3])
        : "r"(a[0]), "r"(a[1]), "r"(a[2]), "r"(a[3]), "r"(b0), "r"(b1));
}

// ---------------------------------------------------------------------------
// convert_x: x -> bf16 hi/lo (same [b][s][i] layout; consecutive-i pairs form
// the packed bf16x2 words the A fragments need).
// ---------------------------------------------------------------------------
__global__ void __launch_bounds__(256) convert_x(const float* __restrict__ x) {
    int p = blockIdx.x * 256 + threadIdx.x;
    if (p >= B_DIM * S_DIM * N_DIM) return;
    float v = x[p];
    __nv_bfloat16 h = __float2bfloat16(v);
    g_xhi[p] = h;
    g_xlo[p] = __float2bfloat16(v - __bfloat162float(h));
}

// ---------------------------------------------------------------------------
// Prep per (b,k): LDL^T -> Cholesky -> half-blocked L^{-1} -> W = L^{-T}, c,
// cst; emit W as bf16 hi/lo packed B-fragment images (g_wqhi/g_wqlo).
// ---------------------------------------------------------------------------
__global__ void __launch_bounds__(128) prep_kernel(const float* __restrict__ mu,
                                                   const float* __restrict__ sigma) {
    __shared__ float A[N_DIM * NP];
    __shared__ float Tb[40 * 41];
    __shared__ float rs[N_DIM];
    __shared__ float lg[N_DIM];
    __shared__ float invj_s;

    int bk = blockIdx.x;
    int tid = threadIdx.x;

    const float* sig = sigma + (size_t)bk * N_DIM * N_DIM;
    for (int p = tid; p < N_DIM * N_DIM; p += 128) {
        int i = p / N_DIM, j = p % N_DIM;
        float v = sig[p];
        if (i == j) v += EPS;
        A[i * NP + j] = v;
    }
    __syncthreads();

    // LDL^T: pivot j, thread t updates trailing column c = j+1+t
    for (int j = 0; j < N_DIM - 1; j++) {
        if (tid == 0) invj_s = 1.0f / A[j * NP + j];
        __syncthreads();
        float invj = invj_s;
        int c = j + 1 + tid;
        if (c < N_DIM) {
            float f = invj * A[c * NP + j];
            #pragma unroll 4
            for (int r = c; r < N_DIM; r++)
                A[r * NP + c] -= A[r * NP + j] * f;
        }
        __syncthreads();
    }

    if (tid < N_DIM) {
        float d = A[tid * NP + tid];
        rs[tid] = rsqrtf(d);
        lg[tid] = 0.5f * logf(d);
    }
    __syncthreads();

    for (int p = tid; p < N_DIM * N_DIM; p += 128) {
        int i = p / N_DIM, j = p % N_DIM;
        if (i >= j) A[i * NP + j] *= rs[j];
    }
    if (tid == 0) {
        float s = 0.f;
        for (int j = 0; j < N_DIM; j++) s += lg[j];
        g_cst[bk] = -s - 0.5f * N_DIM * LOG_2PI;
    }
    __syncthreads();

    // two independent 40x40 triangular inversions (one column per thread)
    if (tid < N_DIM) {
        int j = tid;
        int hi = (j < 40) ? 40 : 80;
        for (int i = j + 1; i < hi; i++) {
            float s = A[i * NP + j] * rs[j];
            for (int t = j + 1; t < i; t++)
                s += A[i * NP + t] * A[j * NP + t];
            A[j * NP + i] = -s * rs[i];
        }
    }
    __syncthreads();

    // Tb = L10 * M00
    for (int p = tid; p < 1600; p += 128) {
        int ii = p / 40, jj = p % 40;
        float s = A[(40 + ii) * NP + jj] * rs[jj];
        for (int t = jj + 1; t < 40; t++)
            s += A[(40 + ii) * NP + t] * A[jj * NP + t];
        Tb[ii * 41 + jj] = s;
    }
    __syncthreads();

    // M10 = -M11 * Tb
    for (int p = tid; p < 1600; p += 128) {
        int ii = p / 40, jj = p % 40;
        float s = rs[40 + ii] * Tb[ii * 41 + jj];
        for (int t = 0; t < ii; t++)
            s += A[(40 + t) * NP + (40 + ii)] * Tb[t * 41 + jj];
        A[jj * NP + (40 + ii)] = -s;
    }
    __syncthreads();

    // c = M * mu   (c_j = sum_{i<=j} mu_i * W[i][j], W[i][j]=M[j][i])
    const float* mub = mu + (size_t)bk * N_DIM;
    if (tid < N_DIM) {
        int j = tid;
        float c = mub[j] * rs[j];
        for (int i = 0; i < j; i++) c += mub[i] * A[i * NP + j];
        g_c[bk * N_DIM + j] = c;
    }
    __syncthreads();

    // Emit packed B fragments. W[k][n]: k<n -> A[k*NP+n]; k==n -> rs[k]; k>n -> 0
    uint2* wh = g_wqhi + (size_t)bk * 1600;
    uint2* wl = g_wqlo + (size_t)bk * 1600;
    for (int p = tid; p < 1600; p += 128) {
        int kc = p / 320;
        int t  = (p / 80) % 4;
        int n  = p % 80;
        int k0 = kc * 16 + 2 * t;
        float w[4];
        #pragma unroll
        for (int q = 0; q < 4; q++) {
            int k = k0 + ((q >= 2) ? 8 : 0) + (q & 1);
            float v = 0.f;
            if (k < n)       v = A[k * NP + n];
            else if (k == n) v = rs[k];
            w[q] = v;
        }
        __nv_bfloat16 h[4], l[4];
        #pragma unroll
        for (int q = 0; q < 4; q++) {
            h[q] = __float2bfloat16(w[q]);
            l[q] = __float2bfloat16(w[q] - __bfloat162float(h[q]));
        }
        wh[p] = make_uint2(pack_bf16(h[0], h[1]), pack_bf16(h[2], h[3]));
        wl[p] = make_uint2(pack_bf16(l[0], l[1]), pack_bf16(l[2], l[3]));
    }
}

// ---------------------------------------------------------------------------
// Main: mma.sync bf16 split-precision GEMM + fused epilogue.
// CTA: 256 thr (8 warps) = 4 m-subtiles(16 rows) x 2 n-halves(40 cols);
// tile = 64 s-rows of batch b. A fragments resident in regs (hi+lo, 5 K-chunks).
// Per k-state: stage B-fragment images to smem, 5n x 5k x 3 mma per warp,
// epilogue: subtract c, square, shfl-reduce, combine halves via smem.
// ---------------------------------------------------------------------------
#define XPHI_OFF 0
#define XP_STRIDE 44
#define XPLO_OFF (64 * XP_STRIDE)           // uint32 units
#define WQHI_OFF 0                          // uint2 units, see base pointers
#define WQ_STRIDE 84
// smem bytes: XP 2*64*44*4 = 22528 ; WQ 2*20*84*8 = 26880 ; QP 2*64*4 = 512
#define SM_XP_BYTES (2 * 64 * XP_STRIDE * 4)
#define SM_WQ_BYTES (2 * 20 * WQ_STRIDE * 8)
#define SM_QP_BYTES (2 * 64 * 4)
#define SM_TOTAL (SM_XP_BYTES + SM_WQ_BYTES + SM_QP_BYTES)

__global__ void __launch_bounds__(256, 2) ll_mma_kernel(float* __restrict__ out) {
    extern __shared__ char smraw[];
    uint32_t* XP   = (uint32_t*)smraw;                         // [2][64][44]
    uint2*    WQ   = (uint2*)(smraw + SM_XP_BYTES);            // [2][20][84]
    float*    QP   = (float*)(smraw + SM_XP_BYTES + SM_WQ_BYTES);  // [2][64]

    int tid = threadIdx.x;
    int wid = tid >> 5, lid = tid & 31;
    int g = lid >> 2, t = lid & 3;            // fragment row-group / col-pair
    int half = wid >> 2;                      // n-half (0: cols 0-39, 1: 40-79)
    int m0 = (wid & 3) * 16;                  // warp's row base within tile
    int b = blockIdx.x, mt = blockIdx.y;
    int s0 = mt * 64;

    // ---- stage x tile (hi/lo) as uint32 (bf16x2 along i), rows OOB -> 0
    {
        const uint32_t* xh = (const uint32_t*)(g_xhi + (size_t)b * S_DIM * N_DIM);
        const uint32_t* xl = (const uint32_t*)(g_xlo + (size_t)b * S_DIM * N_DIM);
        for (int p = tid; p < 64 * 40; p += 256) {
            int m = p / 40, k2 = p % 40;
            int srow = s0 + m;
            uint32_t vh = 0, vl = 0;
            if (srow < S_DIM) {
                vh = xh[srow * 40 + k2];
                vl = xl[srow * 40 + k2];
            }
            XP[m * XP_STRIDE + k2]            = vh;
            XP[XPLO_OFF + m * XP_STRIDE + k2] = vl;
        }
    }
    __syncthreads();

    // ---- load resident A fragments (5 K-chunks, hi+lo)
    uint32_t Ahi[5][4], Alo[5][4];
    #pragma unroll
    for (int kc = 0; kc < 5; kc++) {
        int r0 = (m0 + g) * XP_STRIDE;
        int r1 = (m0 + 8 + g) * XP_STRIDE;
        int c0 = kc * 8 + t, c1 = kc * 8 + 4 + t;
        Ahi[kc][0] = XP[r0 + c0];
        Ahi[kc][1] = XP[r1 + c0];
        Ahi[kc][2] = XP[r0 + c1];
        Ahi[kc][3] = XP[r1 + c1];
        Alo[kc][0] = XP[XPLO_OFF + r0 + c0];
        Alo[kc][1] = XP[XPLO_OFF + r1 + c0];
        Alo[kc][2] = XP[XPLO_OFF + r0 + c1];
        Alo[kc][3] = XP[XPLO_OFF + r1 + c1];
    }

    for (int k = 0; k < K_DIM; k++) {
        int bk = b * K_DIM + k;

        // ---- stage B fragment images for this state
        {
            const uint2* wh = g_wqhi + (size_t)bk * 1600;
            const uint2* wl = g_wqlo + (size_t)bk * 1600;
            for (int p = tid; p < 1600; p += 256) {
                int row = p / 80, n = p % 80;
                WQ[row * WQ_STRIDE + n]                   = wh[p];
                WQ[20 * WQ_STRIDE + row * WQ_STRIDE + n]  = wl[p];
            }
        }
        __syncthreads();

        float qa = 0.f, qb = 0.f;
        const float* cbase = g_c + bk * N_DIM;
        #pragma unroll
        for (int j = 0; j < 5; j++) {
            float d[4] = {0.f, 0.f, 0.f, 0.f};
            int n = half * 40 + j * 8 + g;
            #pragma unroll
            for (int kc = 0; kc < 5; kc++) {
                uint2 bh = WQ[(kc * 4 + t) * WQ_STRIDE + n];
                uint2 bl = WQ[20 * WQ_STRIDE + (kc * 4 + t) * WQ_STRIDE + n];
                mma16816(d, Ahi[kc], bh.x, bh.y);
                mma16816(d, Alo[kc], bh.x, bh.y);
                mma16816(d, Ahi[kc], bl.x, bl.y);
            }
            int col = half * 40 + j * 8 + 2 * t;
            float2 cc = *(const float2*)(cbase + col);
            float e0 = d[0] - cc.x, e1 = d[1] - cc.y;
            float e2 = d[2] - cc.x, e3 = d[3] - cc.y;
            qa = fmaf(e0, e0, qa); qa = fmaf(e1, e1, qa);
            qb = fmaf(e2, e2, qb); qb = fmaf(e3, e3, qb);
        }
        // reduce over t (lanes within row-group)
        qa += __shfl_xor_sync(0xffffffffu, qa, 1);
        qa += __shfl_xor_sync(0xffffffffu, qa, 2);
        qb += __shfl_xor_sync(0xffffffffu, qb, 1);
        qb += __shfl_xor_sync(0xffffffffu, qb, 2);
        if (t == 0) {
            QP[half * 64 + m0 + g]     = qa;
            QP[half * 64 + m0 + 8 + g] = qb;
        }
        __syncthreads();

        if (tid < 64) {
            int srow = s0 + tid;
            if (srow < S_DIM) {
                float quad = QP[tid] + QP[64 + tid];
                out[((size_t)b * S_DIM + srow) * K_DIM + k] =
                    fmaf(-0.5f, quad, g_cst[bk]);
            }
        }
        __syncthreads();   // QP + WQ free for next state
    }
}

// ---------------------------------------------------------------------------
extern "C" void kernel_launch(void* const* d_in, const int* in_sizes, int n_in,
                              void* d_out, int out_size) {
    const float* x     = (const float*)d_in[0];
    const float* mu    = (const float*)d_in[1];
    const float* sigma = (const float*)d_in[2];
    float* out = (float*)d_out;

    convert_x<<<(B_DIM * S_DIM * N_DIM + 255) / 256, 256>>>(x);
    prep_kernel<<<B_DIM * K_DIM, 128>>>(mu, sigma);

    cudaFuncSetAttribute(ll_mma_kernel, cudaFuncAttributeMaxDynamicSharedMemorySize, SM_TOTAL);
    ll_mma_kernel<<<dim3(B_DIM, 16), 256, SM_TOTAL>>>(out);
}